// round 1
// baseline (speedup 1.0000x reference)
#include <cuda_runtime.h>
#include <cstddef>

// Problem constants
#define B_   16
#define S_   2048
#define DM   64
#define HEAD 1024
#define QKVW 3072   // 3 * HEAD

// Scratch: qkv projection output [B, S, 3072] and logits/probs [B, S, S] (in-place softmax)
__device__ float g_qkv[(size_t)B_ * S_ * QKVW];
__device__ float g_L[(size_t)B_ * S_ * S_];

// ---------------------------------------------------------------------------
// Kernel 1: qkv = x @ W   (M = B*S = 32768, K = 64, N = 3072)
// 64x64 tile, 256 threads, 4x4 per thread, K=64 fully resident in smem.
// ---------------------------------------------------------------------------
__global__ void qkv_proj_kernel(const float* __restrict__ x,
                                const float* __restrict__ W) {
    __shared__ float xs[64][65];   // xs[m][k]
    __shared__ float ws[64][65];   // ws[k][n]
    const int m0 = blockIdx.y * 64;
    const int n0 = blockIdx.x * 64;
    const int tid = threadIdx.x;

    for (int i = tid; i < 64 * 64; i += 256) {
        int r = i >> 6, c = i & 63;
        xs[r][c] = x[(size_t)(m0 + r) * DM + c];
        ws[r][c] = W[(size_t)r * QKVW + n0 + c];
    }
    __syncthreads();

    const int tc = tid & 15, tr = tid >> 4;
    float acc[4][4];
#pragma unroll
    for (int i = 0; i < 4; i++)
#pragma unroll
        for (int j = 0; j < 4; j++) acc[i][j] = 0.f;

#pragma unroll 8
    for (int kk = 0; kk < 64; kk++) {
        float a[4], b[4];
#pragma unroll
        for (int i = 0; i < 4; i++) a[i] = xs[tr * 4 + i][kk];
#pragma unroll
        for (int j = 0; j < 4; j++) b[j] = ws[kk][tc * 4 + j];
#pragma unroll
        for (int i = 0; i < 4; i++)
#pragma unroll
            for (int j = 0; j < 4; j++) acc[i][j] += a[i] * b[j];
    }

#pragma unroll
    for (int i = 0; i < 4; i++)
#pragma unroll
        for (int j = 0; j < 4; j++)
            g_qkv[(size_t)(m0 + tr * 4 + i) * QKVW + n0 + tc * 4 + j] = acc[i][j];
}

// ---------------------------------------------------------------------------
// Kernel 2: L = 0.25 * (Q @ K^T) for tiles on/above the diagonal.
// GEMM-NT over the 1024-dim feature axis, 64x64 tile, 16-deep smem chunks.
// Entries with k < q are garbage but never read by the softmax kernel.
// ---------------------------------------------------------------------------
__global__ void qk_kernel() {
    const int bm = blockIdx.y, bn = blockIdx.x, b = blockIdx.z;
    if (bn < bm) return;  // tile fully below the diagonal -> masked, skip

    __shared__ float qs[16][68];   // qs[d][m]
    __shared__ float ks[16][68];   // ks[d][n]
    const int m0 = bm * 64, n0 = bn * 64;
    const float* qbase = g_qkv + (size_t)b * S_ * QKVW;       // q at feature offset 0
    const float* kbase = qbase + HEAD;                        // k at feature offset 1024
    const int tid = threadIdx.x;
    const int tc = tid & 15, tr = tid >> 4;

    float acc[4][4];
#pragma unroll
    for (int i = 0; i < 4; i++)
#pragma unroll
        for (int j = 0; j < 4; j++) acc[i][j] = 0.f;

    for (int d0 = 0; d0 < HEAD; d0 += 16) {
        for (int i = tid; i < 64 * 16; i += 256) {
            int d = i & 15, m = i >> 4;
            qs[d][m] = qbase[(size_t)(m0 + m) * QKVW + d0 + d];
            ks[d][m] = kbase[(size_t)(n0 + m) * QKVW + d0 + d];
        }
        __syncthreads();
#pragma unroll
        for (int d = 0; d < 16; d++) {
            float a[4], bb[4];
            *(float4*)a  = *(const float4*)&qs[d][tr * 4];
            *(float4*)bb = *(const float4*)&ks[d][tc * 4];
#pragma unroll
            for (int i = 0; i < 4; i++)
#pragma unroll
                for (int j = 0; j < 4; j++) acc[i][j] += a[i] * bb[j];
        }
        __syncthreads();
    }

    float* Lrow = g_L + (size_t)b * S_ * S_;
#pragma unroll
    for (int i = 0; i < 4; i++)
#pragma unroll
        for (int j = 0; j < 4; j++)
            Lrow[(size_t)(m0 + tr * 4 + i) * S_ + n0 + tc * 4 + j] = 0.25f * acc[i][j];
}

// ---------------------------------------------------------------------------
// Kernel 3: in-place softmax of row q over keys k in [q, 2048).
// Also zeros k in [q & ~63, q) — exactly the region the PV kernel reads.
// ---------------------------------------------------------------------------
__global__ void softmax_kernel() {
    const int q = blockIdx.x;
    const int b = blockIdx.y;
    float* row = g_L + ((size_t)b * S_ + q) * S_;
    const int tid = threadIdx.x;

    __shared__ float red[8];
    __shared__ float bcast;

    // row max over valid region
    float m = -3.0e38f;
    for (int k = q + tid; k < S_; k += 256) m = fmaxf(m, row[k]);
#pragma unroll
    for (int o = 16; o; o >>= 1) m = fmaxf(m, __shfl_xor_sync(0xffffffffu, m, o));
    if ((tid & 31) == 0) red[tid >> 5] = m;
    __syncthreads();
    if (tid == 0) {
        float v = red[0];
#pragma unroll
        for (int i = 1; i < 8; i++) v = fmaxf(v, red[i]);
        bcast = v;
    }
    __syncthreads();
    m = bcast;

    // exp + sum
    float s = 0.f;
    for (int k = q + tid; k < S_; k += 256) {
        float e = expf(row[k] - m);
        row[k] = e;
        s += e;
    }
#pragma unroll
    for (int o = 16; o; o >>= 1) s += __shfl_xor_sync(0xffffffffu, s, o);
    __syncthreads();   // protect red[] reuse
    if ((tid & 31) == 0) red[tid >> 5] = s;
    __syncthreads();
    if (tid == 0) {
        float v = 0.f;
#pragma unroll
        for (int i = 0; i < 8; i++) v += red[i];
        bcast = 1.0f / v;
    }
    __syncthreads();
    const float inv = bcast;
    for (int k = q + tid; k < S_; k += 256) row[k] *= inv;

    // zero masked entries down to the 64-aligned tile start (read by PV kernel)
    for (int k = (q & ~63) + tid; k < q; k += 256) row[k] = 0.f;
}

// ---------------------------------------------------------------------------
// Kernel 4: out = P @ V per batch  ([2048 x 2048] @ [2048 x 1024]).
// 64x64 tile, 16-deep k chunks; k-loop starts at the tile-aligned diagonal.
// ---------------------------------------------------------------------------
__global__ void pv_kernel(float* __restrict__ out) {
    const int bn = blockIdx.x, bm = blockIdx.y, b = blockIdx.z;
    const int m0 = bm * 64, n0 = bn * 64;

    __shared__ float ps[16][68];   // ps[k][m]
    __shared__ float vs[16][68];   // vs[k][n]
    const float* P = g_L + (size_t)b * S_ * S_;
    const float* vbase = g_qkv + (size_t)b * S_ * QKVW + 2 * HEAD;
    const int tid = threadIdx.x;
    const int tc = tid & 15, tr = tid >> 4;

    float acc[4][4];
#pragma unroll
    for (int i = 0; i < 4; i++)
#pragma unroll
        for (int j = 0; j < 4; j++) acc[i][j] = 0.f;

    for (int k0 = m0; k0 < S_; k0 += 16) {
        for (int i = tid; i < 64 * 16; i += 256) {
            int kk = i & 15, mm = i >> 4;
            ps[kk][mm] = P[(size_t)(m0 + mm) * S_ + k0 + kk];
        }
        for (int i = tid; i < 16 * 64; i += 256) {
            int n = i & 63, kk = i >> 6;
            vs[kk][n] = vbase[(size_t)(k0 + kk) * QKVW + n0 + n];
        }
        __syncthreads();
#pragma unroll
        for (int d = 0; d < 16; d++) {
            float a[4], bb[4];
            *(float4*)a  = *(const float4*)&ps[d][tr * 4];
            *(float4*)bb = *(const float4*)&vs[d][tc * 4];
#pragma unroll
            for (int i = 0; i < 4; i++)
#pragma unroll
                for (int j = 0; j < 4; j++) acc[i][j] += a[i] * bb[j];
        }
        __syncthreads();
    }

#pragma unroll
    for (int i = 0; i < 4; i++)
#pragma unroll
        for (int j = 0; j < 4; j++)
            out[((size_t)b * S_ + m0 + tr * 4 + i) * HEAD + n0 + tc * 4 + j] = acc[i][j];
}

// ---------------------------------------------------------------------------
extern "C" void kernel_launch(void* const* d_in, const int* in_sizes, int n_in,
                              void* d_out, int out_size) {
    const float* x = (const float*)d_in[0];   // [16, 2048, 64]
    const float* W = (const float*)d_in[1];   // [64, 3072]
    float* out = (float*)d_out;               // [16, 2048, 1024]
    (void)in_sizes; (void)n_in; (void)out_size;

    // 1) QKV projection
    {
        dim3 grid(QKVW / 64, (B_ * S_) / 64);   // (48, 512)
        qkv_proj_kernel<<<grid, 256>>>(x, W);
    }
    // 2) Masked, scaled logits (upper-triangular tiles only)
    {
        dim3 grid(S_ / 64, S_ / 64, B_);        // (32, 32, 16)
        qk_kernel<<<grid, 256>>>();
    }
    // 3) Row softmax in place
    {
        dim3 grid(S_, B_);                      // (2048, 16)
        softmax_kernel<<<grid, 256>>>();
    }
    // 4) out = P @ V
    {
        dim3 grid(HEAD / 64, S_ / 64, B_);      // (16, 32, 16)
        pv_kernel<<<grid, 256>>>(out);
    }
}

// round 2
// speedup vs baseline: 1.5772x; 1.5772x over previous
#include <cuda_runtime.h>
#include <cstddef>

// Problem constants
#define B_   16
#define S_   2048
#define DM   64
#define HEAD 1024
#define QKVW 3072   // 3 * HEAD

// Scratch: qkv projection output [B, S, 3072] and logits/probs [B, S, S] (in-place softmax)
__device__ float g_qkv[(size_t)B_ * S_ * QKVW];
__device__ float g_L[(size_t)B_ * S_ * S_];

// ---------------------------------------------------------------------------
// Kernel 1: qkv = x @ W   (M = B*S = 32768, K = 64, N = 3072)
// 128x128 tile, 256 threads, 8x8 per thread, k-chunks of 16.
// ---------------------------------------------------------------------------
__global__ __launch_bounds__(256, 2) void qkv_proj_kernel(const float* __restrict__ x,
                                                          const float* __restrict__ W) {
    __shared__ float xs[16][132];   // xs[k][m]
    __shared__ float ws[16][132];   // ws[k][n]
    const int m0 = blockIdx.y * 128;
    const int n0 = blockIdx.x * 128;
    const int tid = threadIdx.x;
    const int tx = tid & 15, ty = tid >> 4;

    float acc[8][8];
#pragma unroll
    for (int i = 0; i < 8; i++)
#pragma unroll
        for (int j = 0; j < 8; j++) acc[i][j] = 0.f;

    for (int d0 = 0; d0 < DM; d0 += 16) {
        // x chunk: 128 rows x 16 k (contiguous along k)
#pragma unroll
        for (int t = 0; t < 2; t++) {
            int idx = tid + t * 256;
            int row = idx >> 2, dg = (idx & 3) * 4;
            float4 v = *(const float4*)&x[(size_t)(m0 + row) * DM + d0 + dg];
            xs[dg + 0][row] = v.x; xs[dg + 1][row] = v.y;
            xs[dg + 2][row] = v.z; xs[dg + 3][row] = v.w;
        }
        // W chunk: 16 k x 128 n (contiguous along n)
#pragma unroll
        for (int t = 0; t < 2; t++) {
            int idx = tid + t * 256;
            int kk = idx >> 5, ng = (idx & 31) * 4;
            float4 v = *(const float4*)&W[(size_t)(d0 + kk) * QKVW + n0 + ng];
            *(float4*)&ws[kk][ng] = v;
        }
        __syncthreads();
#pragma unroll
        for (int d = 0; d < 16; d++) {
            float a[8], bb[8];
            *(float4*)&a[0]  = *(const float4*)&xs[d][ty * 4];
            *(float4*)&a[4]  = *(const float4*)&xs[d][64 + ty * 4];
            *(float4*)&bb[0] = *(const float4*)&ws[d][tx * 4];
            *(float4*)&bb[4] = *(const float4*)&ws[d][64 + tx * 4];
#pragma unroll
            for (int i = 0; i < 8; i++)
#pragma unroll
                for (int j = 0; j < 8; j++) acc[i][j] += a[i] * bb[j];
        }
        __syncthreads();
    }

#pragma unroll
    for (int i = 0; i < 8; i++) {
        int r = m0 + ((i < 4) ? (ty * 4 + i) : (64 + ty * 4 + i - 4));
        float* o = g_qkv + (size_t)r * QKVW + n0;
        *(float4*)&o[tx * 4]      = *(float4*)&acc[i][0];
        *(float4*)&o[64 + tx * 4] = *(float4*)&acc[i][4];
    }
}

// ---------------------------------------------------------------------------
// Kernel 2: L = 0.25 * (Q @ K^T) for tiles on/above the diagonal.
// GEMM-NT, 128x128 tile, 8x8 per thread, 16-deep smem chunks.
// ---------------------------------------------------------------------------
__global__ __launch_bounds__(256, 2) void qk_kernel() {
    const int bm = blockIdx.y, bn = blockIdx.x, b = blockIdx.z;
    if (bn < bm) return;  // tile fully below the diagonal -> masked, skip

    __shared__ float qs[16][132];   // qs[d][m]
    __shared__ float ks[16][132];   // ks[d][n]
    const int m0 = bm * 128, n0 = bn * 128;
    const float* qbase = g_qkv + (size_t)b * S_ * QKVW;
    const float* kbase = qbase + HEAD;
    const int tid = threadIdx.x;
    const int tx = tid & 15, ty = tid >> 4;

    float acc[8][8];
#pragma unroll
    for (int i = 0; i < 8; i++)
#pragma unroll
        for (int j = 0; j < 8; j++) acc[i][j] = 0.f;

    for (int d0 = 0; d0 < HEAD; d0 += 16) {
#pragma unroll
        for (int t = 0; t < 2; t++) {
            int idx = tid + t * 256;
            int row = idx >> 2, dg = (idx & 3) * 4;
            float4 v = *(const float4*)&qbase[(size_t)(m0 + row) * QKVW + d0 + dg];
            qs[dg + 0][row] = v.x; qs[dg + 1][row] = v.y;
            qs[dg + 2][row] = v.z; qs[dg + 3][row] = v.w;
            float4 u = *(const float4*)&kbase[(size_t)(n0 + row) * QKVW + d0 + dg];
            ks[dg + 0][row] = u.x; ks[dg + 1][row] = u.y;
            ks[dg + 2][row] = u.z; ks[dg + 3][row] = u.w;
        }
        __syncthreads();
#pragma unroll
        for (int d = 0; d < 16; d++) {
            float a[8], bb[8];
            *(float4*)&a[0]  = *(const float4*)&qs[d][ty * 4];
            *(float4*)&a[4]  = *(const float4*)&qs[d][64 + ty * 4];
            *(float4*)&bb[0] = *(const float4*)&ks[d][tx * 4];
            *(float4*)&bb[4] = *(const float4*)&ks[d][64 + tx * 4];
#pragma unroll
            for (int i = 0; i < 8; i++)
#pragma unroll
                for (int j = 0; j < 8; j++) acc[i][j] += a[i] * bb[j];
        }
        __syncthreads();
    }

    float* Lb = g_L + (size_t)b * S_ * S_;
#pragma unroll
    for (int i = 0; i < 8; i++) {
        int r = m0 + ((i < 4) ? (ty * 4 + i) : (64 + ty * 4 + i - 4));
        float* o = Lb + (size_t)r * S_ + n0;
        float4 lo = make_float4(0.25f * acc[i][0], 0.25f * acc[i][1],
                                0.25f * acc[i][2], 0.25f * acc[i][3]);
        float4 hi = make_float4(0.25f * acc[i][4], 0.25f * acc[i][5],
                                0.25f * acc[i][6], 0.25f * acc[i][7]);
        *(float4*)&o[tx * 4]      = lo;
        *(float4*)&o[64 + tx * 4] = hi;
    }
}

// ---------------------------------------------------------------------------
// Kernel 3: in-place softmax of row q over keys k in [q, 2048).
// Also zeros k in [q & ~127, q) — exactly the region the PV kernel reads.
// ---------------------------------------------------------------------------
__global__ void softmax_kernel() {
    const int q = blockIdx.x;
    const int b = blockIdx.y;
    float* row = g_L + ((size_t)b * S_ + q) * S_;
    const int tid = threadIdx.x;

    __shared__ float red[8];
    __shared__ float bcast;

    float m = -3.0e38f;
    for (int k = q + tid; k < S_; k += 256) m = fmaxf(m, row[k]);
#pragma unroll
    for (int o = 16; o; o >>= 1) m = fmaxf(m, __shfl_xor_sync(0xffffffffu, m, o));
    if ((tid & 31) == 0) red[tid >> 5] = m;
    __syncthreads();
    if (tid == 0) {
        float v = red[0];
#pragma unroll
        for (int i = 1; i < 8; i++) v = fmaxf(v, red[i]);
        bcast = v;
    }
    __syncthreads();
    m = bcast;

    float s = 0.f;
    for (int k = q + tid; k < S_; k += 256) {
        float e = expf(row[k] - m);
        row[k] = e;
        s += e;
    }
#pragma unroll
    for (int o = 16; o; o >>= 1) s += __shfl_xor_sync(0xffffffffu, s, o);
    __syncthreads();
    if ((tid & 31) == 0) red[tid >> 5] = s;
    __syncthreads();
    if (tid == 0) {
        float v = 0.f;
#pragma unroll
        for (int i = 0; i < 8; i++) v += red[i];
        bcast = 1.0f / v;
    }
    __syncthreads();
    const float inv = bcast;
    for (int k = q + tid; k < S_; k += 256) row[k] *= inv;

    // zero masked entries down to the 128-aligned tile start (read by PV kernel)
    for (int k = (q & ~127) + tid; k < q; k += 256) row[k] = 0.f;
}

// ---------------------------------------------------------------------------
// Kernel 4: out = P @ V per batch  ([2048 x 2048] @ [2048 x 1024]).
// 128x128 tile, 8x8 per thread; k-loop starts at the tile-aligned diagonal.
// ---------------------------------------------------------------------------
__global__ __launch_bounds__(256, 2) void pv_kernel(float* __restrict__ out) {
    const int bn = blockIdx.x, bm = blockIdx.y, b = blockIdx.z;
    const int m0 = bm * 128, n0 = bn * 128;

    __shared__ float ps[16][132];   // ps[k][m]
    __shared__ float vs[16][132];   // vs[k][n]
    const float* P = g_L + (size_t)b * S_ * S_;
    const float* vbase = g_qkv + (size_t)b * S_ * QKVW + 2 * HEAD;
    const int tid = threadIdx.x;
    const int tx = tid & 15, ty = tid >> 4;

    float acc[8][8];
#pragma unroll
    for (int i = 0; i < 8; i++)
#pragma unroll
        for (int j = 0; j < 8; j++) acc[i][j] = 0.f;

    for (int k0 = m0; k0 < S_; k0 += 16) {
        // P chunk: 128 m x 16 k (contiguous along k) -> transposed into ps[k][m]
#pragma unroll
        for (int t = 0; t < 2; t++) {
            int idx = tid + t * 256;
            int row = idx >> 2, kg = (idx & 3) * 4;
            float4 v = *(const float4*)&P[(size_t)(m0 + row) * S_ + k0 + kg];
            ps[kg + 0][row] = v.x; ps[kg + 1][row] = v.y;
            ps[kg + 2][row] = v.z; ps[kg + 3][row] = v.w;
        }
        // V chunk: 16 k x 128 n (contiguous along n)
#pragma unroll
        for (int t = 0; t < 2; t++) {
            int idx = tid + t * 256;
            int kk = idx >> 5, ng = (idx & 31) * 4;
            float4 v = *(const float4*)&vbase[(size_t)(k0 + kk) * QKVW + n0 + ng];
            *(float4*)&vs[kk][ng] = v;
        }
        __syncthreads();
#pragma unroll
        for (int d = 0; d < 16; d++) {
            float a[8], bb[8];
            *(float4*)&a[0]  = *(const float4*)&ps[d][ty * 4];
            *(float4*)&a[4]  = *(const float4*)&ps[d][64 + ty * 4];
            *(float4*)&bb[0] = *(const float4*)&vs[d][tx * 4];
            *(float4*)&bb[4] = *(const float4*)&vs[d][64 + tx * 4];
#pragma unroll
            for (int i = 0; i < 8; i++)
#pragma unroll
                for (int j = 0; j < 8; j++) acc[i][j] += a[i] * bb[j];
        }
        __syncthreads();
    }

#pragma unroll
    for (int i = 0; i < 8; i++) {
        int r = m0 + ((i < 4) ? (ty * 4 + i) : (64 + ty * 4 + i - 4));
        float* o = out + ((size_t)b * S_ + r) * HEAD + n0;
        *(float4*)&o[tx * 4]      = *(float4*)&acc[i][0];
        *(float4*)&o[64 + tx * 4] = *(float4*)&acc[i][4];
    }
}

// ---------------------------------------------------------------------------
extern "C" void kernel_launch(void* const* d_in, const int* in_sizes, int n_in,
                              void* d_out, int out_size) {
    const float* x = (const float*)d_in[0];   // [16, 2048, 64]
    const float* W = (const float*)d_in[1];   // [64, 3072]
    float* out = (float*)d_out;               // [16, 2048, 1024]
    (void)in_sizes; (void)n_in; (void)out_size;

    // 1) QKV projection
    {
        dim3 grid(QKVW / 128, (B_ * S_) / 128);   // (24, 256)
        qkv_proj_kernel<<<grid, 256>>>(x, W);
    }
    // 2) Masked, scaled logits (upper-triangular tiles only)
    {
        dim3 grid(S_ / 128, S_ / 128, B_);        // (16, 16, 16)
        qk_kernel<<<grid, 256>>>();
    }
    // 3) Row softmax in place
    {
        dim3 grid(S_, B_);                        // (2048, 16)
        softmax_kernel<<<grid, 256>>>();
    }
    // 4) out = P @ V
    {
        dim3 grid(HEAD / 128, S_ / 128, B_);      // (8, 16, 16)
        pv_kernel<<<grid, 256>>>(out);
    }
}

// round 6
// speedup vs baseline: 3.2720x; 2.0746x over previous
#include <cuda_runtime.h>
#include <cuda_bf16.h>
#include <cstdint>
#include <cstddef>

// Problem constants
#define B_   16
#define S_   2048
#define DM   64
#define HEAD 1024
#define QKVW 3072   // 3 * HEAD

// ---------------------------------------------------------------------------
// Scratch (device globals; no runtime allocation allowed)
// ---------------------------------------------------------------------------
__device__ __align__(16) __nv_bfloat16 g_qh[(size_t)B_ * S_ * HEAD];
__device__ __align__(16) __nv_bfloat16 g_ql[(size_t)B_ * S_ * HEAD];
__device__ __align__(16) __nv_bfloat16 g_kh[(size_t)B_ * S_ * HEAD];
__device__ __align__(16) __nv_bfloat16 g_kl[(size_t)B_ * S_ * HEAD];
__device__ __align__(16) float         g_v [(size_t)B_ * S_ * HEAD];
__device__ __align__(16) __nv_bfloat16 g_vth[(size_t)B_ * HEAD * S_];  // V^T hi [b][n][k]
__device__ __align__(16) __nv_bfloat16 g_vtl[(size_t)B_ * HEAD * S_];  // V^T lo
__device__ __align__(16) float         g_L [(size_t)B_ * S_ * S_];     // fp32 logits
__device__ __align__(16) __nv_bfloat16 g_Ph[(size_t)B_ * S_ * S_];     // probs hi
__device__ __align__(16) __nv_bfloat16 g_Pl[(size_t)B_ * S_ * S_];     // probs lo

// ---------------------------------------------------------------------------
// PTX helpers (sm_80-compatible: cp.async, ldmatrix, mma.sync)
// ---------------------------------------------------------------------------
__device__ __forceinline__ uint32_t smem_u32(const void* p) {
    return (uint32_t)__cvta_generic_to_shared(p);
}

__device__ __forceinline__ void cp_async16(uint32_t dst, const void* src) {
    asm volatile("cp.async.cg.shared.global [%0], [%1], 16;"
                 :: "r"(dst), "l"(src) : "memory");
}
__device__ __forceinline__ void cp_commit() {
    asm volatile("cp.async.commit_group;" ::: "memory");
}
__device__ __forceinline__ void cp_wait1() {
    asm volatile("cp.async.wait_group 1;" ::: "memory");
}
__device__ __forceinline__ void cp_wait0() {
    asm volatile("cp.async.wait_group 0;" ::: "memory");
}

__device__ __forceinline__ void ldm_x4(uint32_t* f, uint32_t addr) {
    asm volatile("ldmatrix.sync.aligned.m8n8.x4.shared.b16 {%0,%1,%2,%3}, [%4];"
                 : "=r"(f[0]), "=r"(f[1]), "=r"(f[2]), "=r"(f[3]) : "r"(addr));
}

__device__ __forceinline__ void mma16816(float* c, const uint32_t* a,
                                         uint32_t b0, uint32_t b1) {
    asm volatile(
        "mma.sync.aligned.m16n8k16.row.col.f32.bf16.bf16.f32 "
        "{%0,%1,%2,%3}, {%4,%5,%6,%7}, {%8,%9}, {%0,%1,%2,%3};"
        : "+f"(c[0]), "+f"(c[1]), "+f"(c[2]), "+f"(c[3])
        : "r"(a[0]), "r"(a[1]), "r"(a[2]), "r"(a[3]), "r"(b0), "r"(b1));
}

// ldmatrix lane address inside a 128-row x 128-byte SW128-swizzled tile.
// rowbase: first row of the 16-row block; ks: 16-element k-step (0..3).
__device__ __forceinline__ uint32_t ldm_addr(uint32_t matbase, int rowbase,
                                             int ks, int lane) {
    int j = lane >> 3, r = lane & 7;
    int row = rowbase + (j & 1) * 8 + r;
    uint32_t off = (uint32_t)(row * 128 + ks * 32 + (j >> 1) * 16);
    off ^= (off >> 3) & 0x70;
    return matbase + off;
}

// ---------------------------------------------------------------------------
// split-store helper: fp32 -> (hi, lo) bf16 pairs, 4 at a time (8B stores)
// ---------------------------------------------------------------------------
__device__ __forceinline__ void store_split4(__nv_bfloat16* h, __nv_bfloat16* l,
                                             const float* v) {
    union { __nv_bfloat16 b[4]; uint2 u; } H, L;
#pragma unroll
    for (int r = 0; r < 4; r++) {
        H.b[r] = __float2bfloat16(v[r]);
        L.b[r] = __float2bfloat16(v[r] - __bfloat162float(H.b[r]));
    }
    *(uint2*)h = H.u;
    *(uint2*)l = L.u;
}

// ---------------------------------------------------------------------------
// Kernel 1: qkv = x @ W (fp32), epilogue writes q/k as split-bf16, v as fp32
// ---------------------------------------------------------------------------
__global__ __launch_bounds__(256, 2) void qkv_proj_kernel(const float* __restrict__ x,
                                                          const float* __restrict__ W) {
    __shared__ float xs[16][132];
    __shared__ float ws[16][132];
    const int m0 = blockIdx.y * 128;
    const int n0 = blockIdx.x * 128;
    const int tid = threadIdx.x;
    const int tx = tid & 15, ty = tid >> 4;

    float acc[8][8];
#pragma unroll
    for (int i = 0; i < 8; i++)
#pragma unroll
        for (int j = 0; j < 8; j++) acc[i][j] = 0.f;

    for (int d0 = 0; d0 < DM; d0 += 16) {
#pragma unroll
        for (int t = 0; t < 2; t++) {
            int idx = tid + t * 256;
            int row = idx >> 2, dg = (idx & 3) * 4;
            float4 v = *(const float4*)&x[(size_t)(m0 + row) * DM + d0 + dg];
            xs[dg + 0][row] = v.x; xs[dg + 1][row] = v.y;
            xs[dg + 2][row] = v.z; xs[dg + 3][row] = v.w;
        }
#pragma unroll
        for (int t = 0; t < 2; t++) {
            int idx = tid + t * 256;
            int kk = idx >> 5, ng = (idx & 31) * 4;
            *(float4*)&ws[kk][ng] = *(const float4*)&W[(size_t)(d0 + kk) * QKVW + n0 + ng];
        }
        __syncthreads();
#pragma unroll
        for (int d = 0; d < 16; d++) {
            float a[8], bb[8];
            *(float4*)&a[0]  = *(const float4*)&xs[d][ty * 4];
            *(float4*)&a[4]  = *(const float4*)&xs[d][64 + ty * 4];
            *(float4*)&bb[0] = *(const float4*)&ws[d][tx * 4];
            *(float4*)&bb[4] = *(const float4*)&ws[d][64 + tx * 4];
#pragma unroll
            for (int i = 0; i < 8; i++)
#pragma unroll
                for (int j = 0; j < 8; j++) acc[i][j] += a[i] * bb[j];
        }
        __syncthreads();
    }

    const int region = n0 >> 10;   // 0=q, 1=k, 2=v (128-tiles never straddle)
    const int nn = n0 & 1023;
#pragma unroll
    for (int i = 0; i < 8; i++) {
        int r = m0 + ((i < 4) ? (ty * 4 + i) : (64 + ty * 4 + i - 4));
        if (region == 2) {
            float* o = g_v + (size_t)r * HEAD + nn;
            *(float4*)&o[tx * 4]      = *(float4*)&acc[i][0];
            *(float4*)&o[64 + tx * 4] = *(float4*)&acc[i][4];
        } else {
            __nv_bfloat16* hb = (region == 0 ? g_qh : g_kh) + (size_t)r * HEAD + nn;
            __nv_bfloat16* lb = (region == 0 ? g_ql : g_kl) + (size_t)r * HEAD + nn;
            store_split4(hb + tx * 4,      lb + tx * 4,      &acc[i][0]);
            store_split4(hb + 64 + tx * 4, lb + 64 + tx * 4, &acc[i][4]);
        }
    }
}

// ---------------------------------------------------------------------------
// Kernel 2: transpose + split V: g_v [b*S + m][n] -> g_vth/g_vtl [b][n][m]
// ---------------------------------------------------------------------------
__global__ __launch_bounds__(256) void vtrans_kernel() {
    __shared__ float s[64][65];
    const int m0 = blockIdx.x * 64, n0 = blockIdx.y * 64, b = blockIdx.z;
    const float* src = g_v + ((size_t)(b * S_ + m0)) * HEAD + n0;
    const int tid = threadIdx.x;

#pragma unroll
    for (int t = 0; t < 4; t++) {
        int idx = t * 256 + tid;
        int row = idx >> 4, c4 = (idx & 15) * 4;
        float4 v = *(const float4*)&src[(size_t)row * HEAD + c4];
        s[row][c4] = v.x; s[row][c4 + 1] = v.y; s[row][c4 + 2] = v.z; s[row][c4 + 3] = v.w;
    }
    __syncthreads();

#pragma unroll
    for (int t = 0; t < 4; t++) {
        int idx = t * 256 + tid;
        int n = idx >> 4, m4 = (idx & 15) * 4;
        union { __nv_bfloat16 b[4]; uint2 u; } H, L;
#pragma unroll
        for (int r = 0; r < 4; r++) {
            float v = s[m4 + r][n];
            H.b[r] = __float2bfloat16(v);
            L.b[r] = __float2bfloat16(v - __bfloat162float(H.b[r]));
        }
        size_t o = ((size_t)(b * HEAD + n0 + n)) * S_ + m0 + m4;
        *(uint2*)&g_vth[o] = H.u;
        *(uint2*)&g_vtl[o] = L.u;
    }
}

// ---------------------------------------------------------------------------
// HMMA split-bf16 GEMM, 128x128 CTA tile, K-chunks of 64 bf16.
// 8 warps (2 m x 4 n), each 64x32, m16n8k16 bf16 MMAs, fp32 accum.
// 3 products per k-step: hh + hl + lh (ll dropped, ~2^-16 relative).
//   IS_QK: D = 0.25 * Q K^T -> g_L (fp32)     [skips tiles below diagonal]
//   else : D = P V          -> pv_out (fp32)  [k starts at tile diagonal]
// smem: 2 buffers x 4 matrices x (128 rows x 128B), SW128 swizzled.
// ---------------------------------------------------------------------------
#define MATB   16384
#define BUFB   (4 * MATB)
#define DYNB   (2 * BUFB + 1024)

template <bool IS_QK>
__global__ void __launch_bounds__(256, 1) attn_hmma_kernel(float* __restrict__ pv_out) {
    const int bn = blockIdx.x, bm = blockIdx.y, b = blockIdx.z;
    if (IS_QK && bn < bm) return;   // masked tile

    extern __shared__ __align__(16) char dyn[];
    const uint32_t dynb = smem_u32(dyn);
    const uint32_t tileb = (dynb + 1023) & ~1023u;

    const int tid = threadIdx.x, wid = tid >> 5, lane = tid & 31;
    const int m0 = bm * 128, n0 = bn * 128;
    const int m_off = (wid >> 2) * 64;   // warp rows: 0 or 64
    const int n_off = (wid & 3) * 32;    // warp cols: 0,32,64,96

    const __nv_bfloat16 *Ah, *Al, *Bh, *Bl;
    size_t strd;
    int kstart, NC;
    if (IS_QK) {
        size_t ab = ((size_t)(b * S_ + m0)) * HEAD;
        size_t bb2 = ((size_t)(b * S_ + n0)) * HEAD;
        Ah = g_qh + ab; Al = g_ql + ab; Bh = g_kh + bb2; Bl = g_kl + bb2;
        strd = HEAD; kstart = 0; NC = HEAD / 64;
    } else {
        size_t ab = ((size_t)(b * S_ + m0)) * S_;
        size_t bb2 = ((size_t)(b * HEAD + n0)) * S_;
        Ah = g_Ph + ab; Al = g_Pl + ab; Bh = g_vth + bb2; Bl = g_vtl + bb2;
        strd = S_; kstart = m0; NC = (S_ - m0) / 64;
    }

    float acc[4][4][4];
#pragma unroll
    for (int i = 0; i < 4; i++)
#pragma unroll
        for (int p = 0; p < 4; p++)
#pragma unroll
            for (int r = 0; r < 4; r++) acc[i][p][r] = 0.f;

    // chunk loader: 4 matrices x 128 rows x 64 bf16, SW128 swizzled, cp.async
    auto load_chunk = [&](int c, int buf) {
        const int k0 = kstart + c * 64;
        const __nv_bfloat16* gsrc[4] = { Ah + k0, Al + k0, Bh + k0, Bl + k0 };
#pragma unroll
        for (int mat = 0; mat < 4; mat++) {
            const __nv_bfloat16* g = gsrc[mat];
            uint32_t sb = tileb + buf * BUFB + mat * MATB;
#pragma unroll
            for (int t = 0; t < 4; t++) {
                int idx = t * 256 + tid;
                int row = idx >> 3, pc = idx & 7;
                uint32_t off = (uint32_t)(row * 128 + pc * 16);
                off ^= (off >> 3) & 0x70;
                cp_async16(sb + off, g + (size_t)row * strd + pc * 8);
            }
        }
        cp_commit();
    };

    load_chunk(0, 0);

    for (int c = 0; c < NC; ++c) {
        const int buf = c & 1;
        if (c + 1 < NC) { load_chunk(c + 1, buf ^ 1); cp_wait1(); }
        else            { cp_wait0(); }
        __syncthreads();

        const uint32_t base = tileb + buf * BUFB;
        const uint32_t bAh = base, bAl = base + MATB;
        const uint32_t bBh = base + 2 * MATB, bBl = base + 3 * MATB;

#pragma unroll
        for (int ks = 0; ks < 4; ks++) {
            uint32_t ah[4][4], al[4][4];
#pragma unroll
            for (int i = 0; i < 4; i++) {
                ldm_x4(ah[i], ldm_addr(bAh, m_off + i * 16, ks, lane));
                ldm_x4(al[i], ldm_addr(bAl, m_off + i * 16, ks, lane));
            }
            uint32_t bh[2][4], bl[2][4];
#pragma unroll
            for (int p2 = 0; p2 < 2; p2++) {
                ldm_x4(bh[p2], ldm_addr(bBh, n_off + p2 * 16, ks, lane));
                ldm_x4(bl[p2], ldm_addr(bBl, n_off + p2 * 16, ks, lane));
            }
#pragma unroll
            for (int i = 0; i < 4; i++)
#pragma unroll
                for (int p = 0; p < 4; p++) {
                    const int pr = p >> 1, sb2 = p & 1;
                    mma16816(acc[i][p], ah[i], bh[pr][sb2], bh[pr][2 + sb2]);
                    mma16816(acc[i][p], ah[i], bl[pr][sb2], bl[pr][2 + sb2]);
                    mma16816(acc[i][p], al[i], bh[pr][sb2], bh[pr][2 + sb2]);
                }
        }
        __syncthreads();
    }

    // epilogue: d0,d1 -> (row, col..col+1); d2,d3 -> (row+8, col..col+1)
    const float scale = IS_QK ? 0.25f : 1.0f;
#pragma unroll
    for (int i = 0; i < 4; i++) {
        int gm = m0 + m_off + i * 16 + (lane >> 2);
#pragma unroll
        for (int p = 0; p < 4; p++) {
            int gn = n0 + n_off + p * 8 + (lane & 3) * 2;
            float2 lo = make_float2(scale * acc[i][p][0], scale * acc[i][p][1]);
            float2 hi = make_float2(scale * acc[i][p][2], scale * acc[i][p][3]);
            if (IS_QK) {
                float* d0 = g_L + ((size_t)(b * S_ + gm)) * S_ + gn;
                *(float2*)d0 = lo;
                *(float2*)(d0 + 8 * S_) = hi;
            } else {
                float* d0 = pv_out + ((size_t)(b * S_ + gm)) * HEAD + gn;
                *(float2*)d0 = lo;
                *(float2*)(d0 + 8 * HEAD) = hi;
            }
        }
    }
}

// ---------------------------------------------------------------------------
// Kernel 4: softmax of row q over k in [q, 2048); writes split-bf16 probs
// and zero-fills [q & ~127, q) for the PV kernel.
// ---------------------------------------------------------------------------
__global__ __launch_bounds__(256) void softmax_kernel() {
    const int q = blockIdx.x;
    const int b = blockIdx.y;
    const float* row = g_L + ((size_t)b * S_ + q) * S_;
    __nv_bfloat16* ph = g_Ph + ((size_t)b * S_ + q) * S_;
    __nv_bfloat16* pl = g_Pl + ((size_t)b * S_ + q) * S_;
    const int tid = threadIdx.x;

    __shared__ float red[8];
    __shared__ float bcast;

    float m = -3.0e38f;
    for (int k = q + tid; k < S_; k += 256) m = fmaxf(m, row[k]);
#pragma unroll
    for (int o = 16; o; o >>= 1) m = fmaxf(m, __shfl_xor_sync(0xffffffffu, m, o));
    if ((tid & 31) == 0) red[tid >> 5] = m;
    __syncthreads();
    if (tid == 0) {
        float v = red[0];
#pragma unroll
        for (int i = 1; i < 8; i++) v = fmaxf(v, red[i]);
        bcast = v;
    }
    __syncthreads();
    m = bcast;

    float ev[8];
    float s = 0.f;
    int cnt = 0;
    for (int k = q + tid; k < S_; k += 256) {
        float e = expf(row[k] - m);
        ev[cnt++] = e;
        s += e;
    }
#pragma unroll
    for (int o = 16; o; o >>= 1) s += __shfl_xor_sync(0xffffffffu, s, o);
    __syncthreads();
    if ((tid & 31) == 0) red[tid >> 5] = s;
    __syncthreads();
    if (tid == 0) {
        float v = 0.f;
#pragma unroll
        for (int i = 0; i < 8; i++) v += red[i];
        bcast = 1.0f / v;
    }
    __syncthreads();
    const float inv = bcast;

    cnt = 0;
    for (int k = q + tid; k < S_; k += 256) {
        float p = ev[cnt++] * inv;
        __nv_bfloat16 h = __float2bfloat16(p);
        ph[k] = h;
        pl[k] = __float2bfloat16(p - __bfloat162float(h));
    }
    const __nv_bfloat16 z = __float2bfloat16(0.f);
    for (int k = (q & ~127) + tid; k < q; k += 256) { ph[k] = z; pl[k] = z; }
}

// ---------------------------------------------------------------------------
extern "C" void kernel_launch(void* const* d_in, const int* in_sizes, int n_in,
                              void* d_out, int out_size) {
    const float* x = (const float*)d_in[0];   // [16, 2048, 64]
    const float* W = (const float*)d_in[1];   // [64, 3072]
    float* out = (float*)d_out;               // [16, 2048, 1024]
    (void)in_sizes; (void)n_in; (void)out_size;

    cudaFuncSetAttribute(attn_hmma_kernel<true>,
                         cudaFuncAttributeMaxDynamicSharedMemorySize, DYNB);
    cudaFuncSetAttribute(attn_hmma_kernel<false>,
                         cudaFuncAttributeMaxDynamicSharedMemorySize, DYNB);

    // 1) QKV projection (fp32 compute, split-bf16 q/k, fp32 v)
    {
        dim3 grid(QKVW / 128, (B_ * S_) / 128);   // (24, 256)
        qkv_proj_kernel<<<grid, 256>>>(x, W);
    }
    // 2) V transpose + split
    {
        dim3 grid(S_ / 64, HEAD / 64, B_);        // (32, 16, 16)
        vtrans_kernel<<<grid, 256>>>();
    }
    // 3) logits = 0.25 * Q K^T (HMMA, upper-triangular tiles)
    {
        dim3 grid(S_ / 128, S_ / 128, B_);        // (16, 16, 16)
        attn_hmma_kernel<true><<<grid, 256, DYNB>>>(nullptr);
    }
    // 4) softmax -> split-bf16 probs
    {
        dim3 grid(S_, B_);                        // (2048, 16)
        softmax_kernel<<<grid, 256>>>();
    }
    // 5) out = P V (HMMA)
    {
        dim3 grid(HEAD / 128, S_ / 128, B_);      // (8, 16, 16)
        attn_hmma_kernel<false><<<grid, 256, DYNB>>>(out);
    }
}